// round 1
// baseline (speedup 1.0000x reference)
#include <cuda_runtime.h>
#include <math.h>

#define Bn 16
#define Nn 25000
#define Mn 64
#define TILE 256
#define NB 24
#define NWARPS 8
#define NWPB (NB*NWARPS)   // 192 warp-partials per (b,m)

// ---- scratch (no allocations allowed) ----
__device__ float g_piou[Bn*Mn*NWPB];
__device__ int   g_pidx[Bn*Mn*NWPB];
__device__ float g_biou[Bn*Mn];
__device__ int   g_bidx[Bn*Mn];
__device__ float g_focal0[Bn];

__global__ void k_init(float* out) {
    int t = threadIdx.x;
    if (t < Bn) g_focal0[t] = 0.f;
    if (t == 0) out[0] = 0.f;
}

// Main kernel: per-(b,m) argmax of pairwise IoU + focal(target=0) partial sums.
// Lane l of every warp owns targets l and l+32 (in registers). Each warp streams
// 32 preds of each tile; every lane evaluates its 2 targets vs the broadcast pred.
__global__ __launch_bounds__(256) void k_main(const float* __restrict__ preds,
                                              const float* __restrict__ targets) {
    const int b    = blockIdx.y;
    const int tid  = threadIdx.x;
    const int lane = tid & 31;
    const int warp = tid >> 5;

    __shared__ float4 s_box[TILE];
    __shared__ float  s_area[TILE];
    __shared__ float  s_red[256];

    const float4 t0 = __ldg((const float4*)targets + (b*Mn + lane));
    const float4 t1 = __ldg((const float4*)targets + (b*Mn + lane + 32));
    const float ta0 = (t0.z - t0.x) * (t0.w - t0.y);
    const float ta1 = (t1.z - t1.x) * (t1.w - t1.y);

    float best0 = -1e30f, best1 = -1e30f;
    int   bi0 = Nn, bi1 = Nn;
    float facc = 0.f;

    const float* pb = preds + (size_t)b * Nn * 5;

    for (int base = blockIdx.x * TILE; base < Nn; base += NB * TILE) {
        const int cnt = min(TILE, Nn - base);
        __syncthreads();   // previous tile fully consumed
        {
            // stage + convert: one pred per thread
            float x1, y1, x2, y2, area;
            if (tid < cnt) {
                const float* pr = pb + (size_t)(base + tid) * 5;
                float cx = pr[0], cy = pr[1];
                float w = fmaxf(pr[2], 1e-4f), h = fmaxf(pr[3], 1e-4f);
                float conf = pr[4];
                x1 = cx - 0.5f * w; x2 = cx + 0.5f * w;
                y1 = cy - 0.5f * h; y2 = cy + 0.5f * h;
                area = (x2 - x1) * (y2 - y1);
                // focal loss with target = 0 (exact reference formula)
                float p  = 1.f / (1.f + expf(-conf));
                float ce = fmaxf(conf, 0.f) + log1pf(expf(-fabsf(conf)));
                float pt = fminf(fmaxf(1.f - p, 1e-6f), 1.f - 1e-6f);
                float om = 1.f - pt;
                facc += 0.75f * om * om * ce;
            } else {
                // pad: degenerate far-away box -> iou exactly 0, never wins strict >
                x1 = y1 = x2 = y2 = -3e8f; area = 0.f;
            }
            s_box[tid]  = make_float4(x1, y1, x2, y2);
            s_area[tid] = area;
        }
        __syncthreads();

        const int pbase = base + warp * 32;
        #pragma unroll 8
        for (int k = 0; k < 32; k++) {
            const float4 bx = s_box[warp * 32 + k];   // broadcast LDS
            const float  ar = s_area[warp * 32 + k];
            {
                float iw = fmaxf(fminf(bx.z, t0.z) - fmaxf(bx.x, t0.x), 0.f);
                float ih = fmaxf(fminf(bx.w, t0.w) - fmaxf(bx.y, t0.y), 0.f);
                float inter = iw * ih;
                float iou = __fdividef(inter, ar + ta0 - inter);
                if (iou > best0) { best0 = iou; bi0 = pbase + k; }
            }
            {
                float iw = fmaxf(fminf(bx.z, t1.z) - fmaxf(bx.x, t1.x), 0.f);
                float ih = fmaxf(fminf(bx.w, t1.w) - fmaxf(bx.y, t1.y), 0.f);
                float inter = iw * ih;
                float iou = __fdividef(inter, ar + ta1 - inter);
                if (iou > best1) { best1 = iou; bi1 = pbase + k; }
            }
        }
    }

    const int wg = blockIdx.x * NWARPS + warp;
    g_piou[(b*Mn + lane)      * NWPB + wg] = best0;
    g_pidx[(b*Mn + lane)      * NWPB + wg] = bi0;
    g_piou[(b*Mn + lane + 32) * NWPB + wg] = best1;
    g_pidx[(b*Mn + lane + 32) * NWPB + wg] = bi1;

    // block-reduce focal partial
    s_red[tid] = facc;
    __syncthreads();
    for (int s = 128; s > 0; s >>= 1) {
        if (tid < s) s_red[tid] += s_red[tid + s];
        __syncthreads();
    }
    if (tid == 0) atomicAdd(&g_focal0[b], s_red[0]);
}

// Merge 192 warp-partials per (b,m) -> global argmax with first-index tie-break.
__global__ void k_merge() {
    const int m = blockIdx.x, b = blockIdx.y;
    const float* pi = g_piou + (b*Mn + m) * NWPB;
    const int*   px = g_pidx + (b*Mn + m) * NWPB;
    const int lane = threadIdx.x;
    float bv = -1e30f; int bi = 0x7fffffff;
    for (int i = lane; i < NWPB; i += 32) {
        float v = pi[i]; int id = px[i];
        if (v > bv || (v == bv && id < bi)) { bv = v; bi = id; }
    }
    for (int off = 16; off; off >>= 1) {
        float v = __shfl_xor_sync(0xffffffffu, bv, off);
        int  id = __shfl_xor_sync(0xffffffffu, bi, off);
        if (v > bv || (v == bv && id < bi)) { bv = v; bi = id; }
    }
    if (lane == 0) { g_biou[b*Mn + m] = bv; g_bidx[b*Mn + m] = bi; }
}

// Finalize: greedy dedup (closed form), CIoU for matched pairs, focal corrections,
// per-image loss, atomicAdd of mean into out[0].
__global__ void k_final(const float* __restrict__ preds,
                        const float* __restrict__ targets,
                        float* out) {
    const int b = blockIdx.x, m = threadIdx.x;   // 64 threads
    __shared__ float s_iou[Mn];
    __shared__ int   s_idx[Mn];
    __shared__ float s_ci[Mn], s_fd[Mn];
    __shared__ int   s_ok[Mn];

    s_iou[m] = g_biou[b*Mn + m];
    s_idx[m] = g_bidx[b*Mn + m];
    __syncthreads();

    bool ok = s_iou[m] > 0.2f;
    if (ok) {
        const int my = s_idx[m];
        for (int mp = 0; mp < m; mp++)
            if (s_idx[mp] == my && s_iou[mp] > 0.2f) { ok = false; break; }
    }

    float ci = 0.f, fd = 0.f;
    if (ok) {
        const int p = s_idx[m];
        const float* pr = preds + ((size_t)b*Nn + p) * 5;
        float cx = pr[0], cy = pr[1];
        float w = fmaxf(pr[2], 1e-4f), h = fmaxf(pr[3], 1e-4f);
        float conf = pr[4];
        float x1p = cx - 0.5f*w, x2p = cx + 0.5f*w;
        float y1p = cy - 0.5f*h, y2p = cy + 0.5f*h;
        float4 t = __ldg((const float4*)targets + (b*Mn + m));
        float x1t = t.x, y1t = t.y, x2t = t.z, y2t = t.w;

        float inter = fmaxf(fminf(x2p,x2t) - fmaxf(x1p,x1t), 0.f)
                    * fmaxf(fminf(y2p,y2t) - fmaxf(y1p,y1t), 0.f);
        float un  = (x2p-x1p)*(y2p-y1p) + (x2t-x1t)*(y2t-y1t) - inter;
        float iou = inter / (un + 1e-7f);
        float cw = fmaxf(x2p,x2t) - fminf(x1p,x1t);
        float ch = fmaxf(y2p,y2t) - fminf(y1p,y1t);
        float diag = cw*cw + ch*ch + 1e-7f;
        float dx = x1p + x2p - x1t - x2t;
        float dy = y1p + y2p - y1t - y2t;
        float centers = (dx*dx + dy*dy) * 0.25f;
        float wp = x2p - x1p, hp = y2p - y1p;
        float wt = x2t - x1t, ht = y2t - y1t;
        float dv = atanf(wt/ht) - atanf(wp/hp);
        float v  = (float)(4.0/(M_PI*M_PI)) * dv * dv;
        float alpha = v / (1.f - iou + v + 1e-7f);
        ci = 1.f - iou + centers/diag + alpha*v;

        // focal(target=1) - focal(target=0) correction for this pred
        float pp  = 1.f / (1.f + expf(-conf));
        float l1e = log1pf(expf(-fabsf(conf)));
        float ce1 = fmaxf(conf, 0.f) - conf + l1e;
        float ce0 = fmaxf(conf, 0.f) + l1e;
        float pt1 = fminf(fmaxf(pp,       1e-6f), 1.f - 1e-6f);
        float pt0 = fminf(fmaxf(1.f - pp, 1e-6f), 1.f - 1e-6f);
        float a1 = 1.f - pt1, a0 = 1.f - pt0;
        fd = 0.25f*a1*a1*ce1 - 0.75f*a0*a0*ce0;
    }

    s_ci[m] = ci; s_fd[m] = fd; s_ok[m] = ok ? 1 : 0;
    __syncthreads();

    if (m == 0) {
        float sc = 0.f, sf = 0.f; int n = 0;
        for (int i = 0; i < Mn; i++) { sc += s_ci[i]; sf += s_fd[i]; n += s_ok[i]; }
        float conf_loss = (g_focal0[b] + sf) / (float)Nn;
        float box = (n > 0) ? sc / (float)n : 0.f;
        atomicAdd(out, (conf_loss + box) * (1.f / (float)Bn));
    }
}

extern "C" void kernel_launch(void* const* d_in, const int* in_sizes, int n_in,
                              void* d_out, int out_size) {
    const float* preds   = (const float*)d_in[0];
    const float* targets = (const float*)d_in[1];
    float* out = (float*)d_out;

    k_init <<<1, 32>>>(out);
    k_main <<<dim3(NB, Bn), 256>>>(preds, targets);
    k_merge<<<dim3(Mn, Bn), 32>>>();
    k_final<<<Bn, Mn>>>(preds, targets, out);
}